// round 15
// baseline (speedup 1.0000x reference)
#include <cuda_runtime.h>
#include <math.h>

#define NB 8
#define NA 21504
#define NG 60
#define NC 15
#define BA (NB*NA)
#define NBG (NB*NG)
#define L0N 16384
#define L1N 20480
#define LOG4F 1.3862943611198906f
#define FULLM 0xffffffffu
#define NSEG 16
#define MAXFG 4800
#define CINIT 990000.0f

// ---------------- static device scratch ----------------
__device__ float g_bx[BA], g_by[BA];
__device__ float g_a2[BA], g_b2[BA], g_c2[BA], g_d2s[BA], g_ld2[BA];
__device__ float g_obj[BA], g_S[BA];
__device__ float g_lc[NC*BA];                    // [c][b*A+a] (cand anchors only)
__device__ float2 g_ic[(size_t)NBG*NA];          // compacted {iou, cost}: [b][g][slot]
__device__ int   g_ci[BA];                       // compacted cand anchor idx: [b][slot]
__device__ unsigned long long g_bothA[BA];       // compacted both-bits: [b][slot]
__device__ int   g_ccnt[NB];
__device__ float g_gcx[NBG], g_gcy[NBG], g_ghw[NBG], g_ghh[NBG];
__device__ float g_ga1[NBG], g_gb1[NBG], g_gc1[NBG], g_gd1s[NBG], g_gld1[NBG];
__device__ int   g_gcls[NBG], g_gvalid[NBG];
__device__ float g_pt[NBG*NSEG*10];
__device__ float g_pc[NBG*NSEG*10];
__device__ int   g_pi[NBG*NSEG*10];
__device__ float g_pv[NBG*NSEG*10];
__device__ int   g_cnt[BA];
__device__ int   g_mg[BA];
__device__ float g_miou[BA];
__device__ int   g_nfg;
__device__ int   g_done;
__device__ int   g_fgl[MAXFG];
__device__ float g_acc[5];

// ---------------- deterministic pair cost ----------------
__device__ __forceinline__ void pair_cost(
    float ga, float gb, float gc, float gcx, float gcy, float gld1,
    float a2, float b2, float c2, float bx, float by, float lbase,
    float S, float lc, float pb,
    float& iou, float& cost)
{
    float Af = __fadd_rn(ga, a2);
    float Bf = __fadd_rn(gb, b2);
    float Cf = __fadd_rn(gc, c2);
    float dx = __fsub_rn(gcx, bx);
    float dy = __fsub_rn(gcy, by);
    float cc = __fmul_rn(Cf, Cf);
    float den = __fadd_rn(__fmaf_rn(Af, Bf, -cc), 1e-8f);
    float rden = __fdividef(1.f, den);
    float dx2 = __fmul_rn(dx, dx);
    float dy2 = __fmul_rn(dy, dy);
    float t1 = __fmul_rn(__fmul_rn(0.25f, __fmaf_rn(Af, dy2, __fmul_rn(Bf, dx2))), rden);
    float t2 = __fmul_rn(__fmul_rn(-0.5f, __fmul_rn(Cf, __fmul_rn(dx, dy))), rden);
    float t3 = __fmul_rn(0.5f, __fsub_rn(__logf(den), __fadd_rn(gld1, lbase)));
    float bd = fminf(fmaxf(__fadd_rn(__fadd_rn(t1, t2), t3), 1e-8f), 100.f);
    float q = fminf(fmaxf(__fsub_rn(1.f, __expf(-bd)), 1e-20f), 1.f);
    iou = __fsub_rn(1.f, __fmul_rn(q, __frsqrt_rn(q)));
    float base = __fadd_rn(__fadd_rn(S, lc), pb);
    cost = __fmaf_rn(-3.f, __logf(__fadd_rn(iou, 1e-8f)), base);
}

// ---------------- K1b: GT prep + zero accumulators (1 block) ----------------
__global__ void k_gt(const float* __restrict__ labels) {
    int t = threadIdx.x;
    if (t < 5) g_acc[t] = 0.f;
    if (t == 5) g_nfg = 0;
    if (t == 6) g_done = 0;
    if (t >= 8 && t < 8 + NB) g_ccnt[t - 8] = 0;
    __syncthreads();
    if (t >= NBG) return;
    const float* L = labels + (size_t)t * 6;
    float l0 = L[0], l1 = L[1], l2 = L[2], l3 = L[3], l4 = L[4], l5 = L[5];
    float sum = l0 + l1 + l2 + l3 + l4 + l5;
    int valid = (sum > 0.f) ? 1 : 0;
    float sn, cs; __sincosf(l5, &sn, &cs);
    float w2 = l3*l3/12.0f, h2 = l4*l4/12.0f;
    float a1 = w2*cs*cs + h2*sn*sn;
    float b1 = w2*sn*sn + h2*cs*cs;
    float c1 = (w2 - h2) * cs * sn;
    float d1 = fmaxf(a1*b1 - c1*c1, 0.f);
    float d1s = d1 * __frsqrt_rn(fmaxf(d1, 1e-30f));
    g_gcx[t] = l1; g_gcy[t] = l2;
    g_ghw[t] = 0.5f * l3; g_ghh[t] = 0.5f * l4;
    g_ga1[t] = a1; g_gb1[t] = b1; g_gc1[t] = c1;
    g_gd1s[t] = d1s;
    g_gld1[t] = __logf(fmaxf(d1s, 1e-35f));
    g_gcls[t] = (int)l0;
    g_gvalid[t] = valid;
    if (valid) atomicAdd(&g_acc[4], 1.f);
}

// ---------------- K1: decode + cand/both + compaction + obj-BCE fold ----------------
__global__ void k_decode(const float* __restrict__ o8,
                         const float* __restrict__ o16,
                         const float* __restrict__ o32) {
    int t = blockIdx.x * blockDim.x + threadIdx.x;
    int b = t / NA;
    int a = t - b * NA;
    int tid = threadIdx.x;
    int lane = tid & 31;
    g_cnt[t] = 0;
    __shared__ float s_cx[NG], s_cy[NG], s_hw[NG], s_hh[NG];
    if (tid < NG) {
        int gi = b * NG + tid;
        int v = g_gvalid[gi];
        s_cx[tid] = v ? g_gcx[gi] : 3.0e9f;
        s_cy[tid] = v ? g_gcy[gi] : 3.0e9f;
        s_hw[tid] = g_ghw[gi]; s_hh[tid] = g_ghh[gi];
    }
    __syncthreads();
    const float* src; int hw, i; float st; int gx, gy;
    if (a < L0N)       { src = o8;  hw = 16384; i = a;        st = 8.f;  gx = i & 127; gy = i >> 7; }
    else if (a < L1N)  { src = o16; hw = 4096;  i = a - L0N;  st = 16.f; gx = i & 63;  gy = i >> 6; }
    else               { src = o32; hw = 1024;  i = a - L1N;  st = 32.f; gx = i & 31;  gy = i >> 5; }
    const float* p0 = src + (size_t)b * 21 * hw + i;
    float r0 = p0[0], r1 = p0[hw], r2 = p0[2*hw], r3 = p0[3*hw], r4 = p0[4*hw], r5 = p0[5*hw];
    float bx = (r0 + (float)gx) * st;
    float by = (r1 + (float)gy) * st;
    float bw = __expf(r2) * st;
    float bh = __expf(r3) * st;
    float sn, cs; __sincosf(r4, &sn, &cs);
    float w2 = bw * bw / 12.0f, h2 = bh * bh / 12.0f;
    float a2 = w2*cs*cs + h2*sn*sn;
    float b2 = w2*sn*sn + h2*cs*cs;
    float c2 = (w2 - h2) * cs * sn;
    float d2 = fmaxf(a2*b2 - c2*c2, 0.f);
    float d2s = d2 * __frsqrt_rn(fmaxf(d2, 1e-30f));
    g_bx[t] = bx; g_by[t] = by;
    g_a2[t] = a2; g_b2[t] = b2; g_c2[t] = c2;
    g_d2s[t] = d2s;
    g_ld2[t] = __logf(fmaxf(d2s, 1e-35f));
    g_obj[t] = r5;

    // cand / both (geometry only; GTs ready from k_gt)
    float xc = ((float)gx + 0.5f) * st;
    float yc = ((float)gy + 0.5f) * st;
    float rad = 2.5f * st;
    unsigned long long both = 0ULL;
    bool cand = false;
    #pragma unroll 4
    for (int g = 0; g < NG; g++) {
        float dx = fabsf(xc - s_cx[g]);
        float dy = fabsf(yc - s_cy[g]);
        bool ib = (dx < s_hw[g]) & (dy < s_hh[g]);
        bool ic = (dx < rad) & (dy < rad);
        cand |= ib | ic;
        if (ib & ic) both |= (1ULL << g);
    }
    unsigned mask = __ballot_sync(FULLM, cand);
    if (mask) {
        int base;
        if (lane == 0) base = atomicAdd(&g_ccnt[b], __popc(mask));
        base = __shfl_sync(FULLM, base, 0);
        if (cand) {
            int slot = base + __popc(mask & ((1u << lane) - 1u));
            g_ci[b * NA + slot] = a;
            g_bothA[b * NA + slot] = both;
        }
    }
    // class-cost precompute: cand anchors only (non-cand g_lc/g_S never read)
    if (cand) {
        float so = __fdividef(1.f, 1.f + __expf(-r5));
        float S = 0.f;
        #pragma unroll
        for (int c = 0; c < NC; c++) {
            float x = p0[(6 + c) * hw];
            float sc = __fdividef(1.f, 1.f + __expf(-x));
            float q = sc * so;
            float p = q * __frsqrt_rn(fmaxf(q, 1e-30f));
            p = fminf(fmaxf(p, 1e-7f), 1.f - 1e-7f);
            float lg = __logf(1.f - p);
            float lp = __logf(p);
            S -= lg;
            g_lc[c * BA + t] = lg - lp;
        }
        g_S[t] = S;
    }
    // obj BCE vs target 0 over ALL anchors
    float lo = fmaxf(r5, 0.f) + __logf(1.f + __expf(-fabsf(r5)));
    #pragma unroll
    for (int o = 16; o > 0; o >>= 1) lo += __shfl_down_sync(FULLM, lo, o);
    __shared__ float sred[4];
    int w = tid >> 5;
    if (lane == 0) sred[w] = lo;
    __syncthreads();
    if (tid == 0)
        atomicAdd(&g_acc[1], sred[0] + sred[1] + sred[2] + sred[3]);
}

// ---------------- K2: cost over compacted slots (grid-stride) ----------------
__global__ void k_cost() {
    int b = blockIdx.x / 84;
    int blk = blockIdx.x - b * 84;
    int tid = threadIdx.x;
    __shared__ float s_cx[NG], s_cy[NG];
    __shared__ float s_a1[NG], s_b1[NG], s_c1[NG], s_ld1[NG];
    __shared__ int   s_cls[NG], s_val[NG];
    if (tid < NG) {
        int gi = b * NG + tid;
        s_val[tid] = g_gvalid[gi];
        s_cx[tid] = g_gcx[gi]; s_cy[tid] = g_gcy[gi];
        s_a1[tid] = g_ga1[gi]; s_b1[tid] = g_gb1[gi];
        s_c1[tid] = g_gc1[gi]; s_ld1[tid] = g_gld1[gi];
        s_cls[tid] = g_gcls[gi];
    }
    __syncthreads();
    int cnt = g_ccnt[b];
    for (int slot = blk * 128 + tid; slot < cnt; slot += 84 * 128) {
        int a = g_ci[b * NA + slot];
        int t = b * NA + a;
        unsigned long long both = g_bothA[b * NA + slot];
        float bx = g_bx[t], by = g_by[t];
        float a2 = g_a2[t], b2 = g_b2[t], c2 = g_c2[t];
        float S = g_S[t];
        float lbase = g_ld2[t] + LOG4F;
        size_t rowbase = (size_t)b * NG * NA + slot;
        for (int g = 0; g < NG; g++) {
            if (!s_val[g]) continue;
            float lc = g_lc[s_cls[g] * BA + t];
            float pb = ((both >> g) & 1ULL) ? 0.f : 1e5f;
            float iou, cost;
            pair_cost(s_a1[g], s_b1[g], s_c1[g], s_cx[g], s_cy[g], s_ld1[g],
                      a2, b2, c2, bx, by, lbase, S, lc, pb, iou, cost);
            g_ic[rowbase + (size_t)g * NA] = make_float2(iou, cost);
        }
    }
}

// ---------------- selection helpers ----------------
__device__ __forceinline__ bool pless(float c1, int i1, float c2, int i2) {
    return (c1 < c2) || (c1 == c2 && i1 < i2);
}
__device__ __forceinline__ void wins_top(float& tv, int lane, float c) {
    unsigned bm = __ballot_sync(FULLM, (lane < 10) && (c > tv)) & 0x3FFu;
    if (bm) {
        int p = __ffs(bm) - 1;
        float up = __shfl_up_sync(FULLM, tv, 1);
        if (lane < 10 && lane >= p) tv = (lane == p) ? c : up;
    }
}
__device__ __forceinline__ void wins_bot3(float& bcv, int& biv, float& bov,
                                          int lane, float c, int i, float io) {
    unsigned bm = __ballot_sync(FULLM, (lane < 10) && pless(c, i, bcv, biv)) & 0x3FFu;
    if (bm) {
        int p = __ffs(bm) - 1;
        float uc = __shfl_up_sync(FULLM, bcv, 1);
        int   ui = __shfl_up_sync(FULLM, biv, 1);
        float uo = __shfl_up_sync(FULLM, bov, 1);
        if (lane < 10 && lane >= p) {
            bcv = (lane == p) ? c : uc;
            biv = (lane == p) ? i : ui;
            bov = (lane == p) ? io : uo;
        }
    }
}

// ---------------- K3a: partials over compacted list (depth-2 prefetch) ----------------
__global__ void k_sel1() {
    int bg = blockIdx.x >> 2;
    int part = blockIdx.x & 3;
    if (!g_gvalid[bg]) return;
    int w = threadIdx.x >> 5, lane = threadIdx.x & 31;
    int seg = part * 4 + w;
    int b = bg / NG;
    int cnt = g_ccnt[b];
    const float2* __restrict__ row = g_ic + (size_t)bg * NA;
    const int* __restrict__ ci = g_ci + b * NA;

    float tv = 0.f; float bcv = CINIT; int biv = 0x7fffffff; float bov = 0.f;
    float thr_t = 0.f; float thr_c = CINIT; int thr_i = 0x7fffffff;

    const int stride = NSEG * 32;
    int s0 = seg * 32 + lane;
    int nIter = 0;
    if (cnt > seg * 32) nIter = (cnt - seg * 32 + stride - 1) / stride;  // warp-uniform

    float2 f0 = make_float2(0.f, 3.0e38f), f1 = make_float2(0.f, 3.0e38f);
    int i0 = 0x7fffffff, i1 = 0x7fffffff;
    if (nIter > 0 && s0 < cnt) { f0 = row[s0]; i0 = ci[s0]; }
    if (nIter > 1 && s0 + stride < cnt) { f1 = row[s0 + stride]; i1 = ci[s0 + stride]; }

    for (int it = 0; it < nIter; it++) {
        float2 f2 = make_float2(0.f, 3.0e38f);
        int i2 = 0x7fffffff;
        int pslot = s0 + (it + 2) * stride;
        if (it + 2 < nIter && pslot < cnt) { f2 = row[pslot]; i2 = ci[pslot]; }
        float e = f0.x;
        float c = f0.y;
        int idx = i0;
        unsigned mt = __ballot_sync(FULLM, e > thr_t);
        unsigned mc = __ballot_sync(FULLM, (c < thr_c) || (c == thr_c && idx <= thr_i));
        if (mt) {
            do {
                int sidx = __ffs(mt) - 1; mt &= mt - 1;
                wins_top(tv, lane, __shfl_sync(FULLM, e, sidx));
            } while (mt);
            thr_t = __shfl_sync(FULLM, tv, 9);
        }
        if (mc) {
            do {
                int sidx = __ffs(mc) - 1; mc &= mc - 1;
                wins_bot3(bcv, biv, bov, lane,
                          __shfl_sync(FULLM, c, sidx), __shfl_sync(FULLM, idx, sidx),
                          __shfl_sync(FULLM, e, sidx));
            } while (mc);
            thr_c = __shfl_sync(FULLM, bcv, 9);
            thr_i = __shfl_sync(FULLM, biv, 9);
        }
        f0 = f1; i0 = i1;
        f1 = f2; i1 = i2;
    }
    if (lane < 10) {
        int o = (bg * NSEG + seg) * 10 + lane;
        g_pt[o] = tv; g_pc[o] = bcv; g_pi[o] = biv; g_pv[o] = bov;
    }
}

// ---------------- K3b: merge partials; dyn_k; scatter matched anchors ----------------
__global__ void k_sel2() {
    int bg = blockIdx.x;
    int lane = threadIdx.x;
    if (!g_gvalid[bg]) return;
    int b = bg / NG, g = bg - b * NG;
    const float* __restrict__ pt  = g_pt + (size_t)bg * NSEG * 10;
    const float* __restrict__ pcr = g_pc + (size_t)bg * NSEG * 10;
    const int*   __restrict__ pir = g_pi + (size_t)bg * NSEG * 10;
    const float* __restrict__ pvr = g_pv + (size_t)bg * NSEG * 10;

    float tv = 0.f, bcv = CINIT, bov = 0.f; int biv = 0x7fffffff;
    float thr_t = 0.f, thr_c = CINIT; int thr_i = 0x7fffffff;
    #pragma unroll
    for (int i = 0; i < 5; i++) {
        int e = i * 32 + lane;
        bool ok = e < NSEG * 10;
        float a = ok ? pt[e]  : 0.f;
        float c = ok ? pcr[e] : 3.0e38f;
        int  ix = ok ? pir[e] : 0x7fffffff;
        float io = ok ? pvr[e] : 0.f;
        unsigned mt = __ballot_sync(FULLM, a > thr_t);
        unsigned mc = __ballot_sync(FULLM, (c < thr_c) || (c == thr_c && ix < thr_i));
        while (mt) {
            int sidx = __ffs(mt) - 1; mt &= mt - 1;
            wins_top(tv, lane, __shfl_sync(FULLM, a, sidx));
        }
        thr_t = __shfl_sync(FULLM, tv, 9);
        while (mc) {
            int sidx = __ffs(mc) - 1; mc &= mc - 1;
            wins_bot3(bcv, biv, bov, lane,
                      __shfl_sync(FULLM, c, sidx), __shfl_sync(FULLM, ix, sidx),
                      __shfl_sync(FULLM, io, sidx));
        }
        thr_c = __shfl_sync(FULLM, bcv, 9);
        thr_i = __shfl_sync(FULLM, biv, 9);
    }
    float x = (lane < 10) ? tv : 0.f;
    #pragma unroll
    for (int o = 16; o > 0; o >>= 1) x += __shfl_xor_sync(FULLM, x, o);
    int k = (int)x;
    if (k < 1) k = 1;
    if (k > 10) k = 10;
    if (lane < k) {
        int t = b * NA + biv;
        int old = atomicAdd(&g_cnt[t], 1);
        if (old == 0) {
            g_mg[t] = g;
            g_miou[t] = bov;
            int pos = atomicAdd(&g_nfg, 1);
            g_fgl[pos] = t;
        }
    }
}

// ---------------- K5: losses over fg anchors + fused finalize ----------------
__global__ void k_fgloss(const float* __restrict__ o8,
                         const float* __restrict__ o16,
                         const float* __restrict__ o32,
                         float* __restrict__ out, int n) {
    int i = blockIdx.x * blockDim.x + threadIdx.x;
    int nfg = g_nfg;
    float liou = 0.f, lcls = 0.f, lobjc = 0.f, fo = 0.f;
    if (i < nfg) {
        int t = g_fgl[i];
        int b = t / NA;
        int a = t - b * NA;
        int cnt = g_cnt[t];
        int mg; float pi;
        if (cnt == 1) { mg = g_mg[t]; pi = g_miou[t]; }
        else {
            float st; int lvlbase, shx, mskx;
            if (a < L0N)      { st = 8.f;  lvlbase = 0;    shx = 7; mskx = 127; }
            else if (a < L1N) { st = 16.f; lvlbase = L0N;  shx = 6; mskx = 63; }
            else              { st = 32.f; lvlbase = L1N;  shx = 5; mskx = 31; }
            int ii = a - lvlbase;
            float xc = ((float)(ii & mskx) + 0.5f) * st;
            float yc = ((float)(ii >> shx) + 0.5f) * st;
            float rad = 2.5f * st;
            float bx = g_bx[t], by = g_by[t];
            float a2 = g_a2[t], b2 = g_b2[t], c2 = g_c2[t];
            float S = g_S[t];
            float lbase = g_ld2[t] + LOG4F;
            float minc = 3.4e38f; mg = 0; pi = 0.f;
            for (int g = 0; g < NG; g++) {
                int gi = b * NG + g;
                if (!g_gvalid[gi]) continue;
                float gcx = g_gcx[gi], gcy = g_gcy[gi];
                float dxa = fabsf(xc - gcx), dya = fabsf(yc - gcy);
                bool ib = (dxa < g_ghw[gi]) & (dya < g_ghh[gi]);
                bool ic = (dxa < rad) & (dya < rad);
                float pb = (ib & ic) ? 0.f : 1e5f;
                float lc = g_lc[g_gcls[gi] * BA + t];
                float iou, cost;
                pair_cost(g_ga1[gi], g_gb1[gi], g_gc1[gi], gcx, gcy, g_gld1[gi],
                          a2, b2, c2, bx, by, lbase, S, lc, pb, iou, cost);
                if (cost < minc) { minc = cost; mg = g; pi = iou; }
            }
        }
        int gi = b * NG + mg;
        {
            float bx = g_bx[t], by = g_by[t];
            float a2 = g_a2[t], b2 = g_b2[t], c2 = g_c2[t], d2s = g_d2s[t];
            float Af = a2 + g_ga1[gi], Bf = b2 + g_gb1[gi], Cf = c2 + g_gc1[gi];
            float dx = bx - g_gcx[gi], dy = by - g_gcy[gi];
            float den = Af * Bf - Cf * Cf + 1e-8f;
            float rden = __fdividef(1.f, den);
            float t1 = 0.25f * (Af*dy*dy + Bf*dx*dx) * rden;
            float t2 = -0.5f * Cf * dx * dy * rden;
            float t3 = 0.5f * __logf(__fdividef(den, 4.f * g_gd1s[gi] * d2s + 1e-8f));
            float bd = fminf(fmaxf(t1 + t2 + t3, 1e-8f), 100.f);
            float q = fminf(fmaxf(1.f - __expf(-bd), 1e-20f), 1.f);
            float ioum = 1.f - q * __frsqrt_rn(q);
            liou = 1.f - ioum;
        }
        {
            const float* src; int hw, idx;
            if (a < L0N)      { src = o8;  hw = 16384; idx = a; }
            else if (a < L1N) { src = o16; hw = 4096;  idx = a - L0N; }
            else              { src = o32; hw = 1024;  idx = a - L1N; }
            const float* pc = src + ((size_t)b * 21 + 6) * hw + idx;
            int mcls = g_gcls[gi];
            #pragma unroll
            for (int c = 0; c < NC; c++) {
                float x = pc[(size_t)c * hw];
                float tg = (c == mcls) ? pi : 0.f;
                lcls += fmaxf(x, 0.f) - x * tg + __logf(1.f + __expf(-fabsf(x)));
            }
        }
        lobjc = -g_obj[t];
        fo = 1.f;
    }
    #pragma unroll
    for (int o = 16; o > 0; o >>= 1) {
        liou  += __shfl_down_sync(FULLM, liou, o);
        lcls  += __shfl_down_sync(FULLM, lcls, o);
        lobjc += __shfl_down_sync(FULLM, lobjc, o);
        fo    += __shfl_down_sync(FULLM, fo, o);
    }
    if ((threadIdx.x & 31) == 0) {
        atomicAdd(&g_acc[0], liou);
        atomicAdd(&g_acc[1], lobjc);
        atomicAdd(&g_acc[2], lcls);
        atomicAdd(&g_acc[3], fo);
    }
    __syncthreads();
    if (threadIdx.x == 0) {
        __threadfence();
        int prev = atomicAdd(&g_done, 1);
        if (prev == gridDim.x - 1) {
            float nf2 = g_acc[3];
            float nf = fmaxf(nf2, 1.f);
            float li = g_acc[0] / nf;
            float lo = g_acc[1] / nf;
            float lc2 = g_acc[2] / nf;
            float li5 = 5.f * li;
            if (n > 0) out[0] = li5 + lo + lc2;
            if (n > 1) out[1] = li5;
            if (n > 2) out[2] = lo;
            if (n > 3) out[3] = lc2;
            if (n > 4) out[4] = 0.f;
            if (n > 5) out[5] = nf2 / fmaxf(g_acc[4], 1.f);
            for (int j = 6; j < n; j++) out[j] = 0.f;
        }
    }
}

// ---------------- launch ----------------
extern "C" void kernel_launch(void* const* d_in, const int* in_sizes, int n_in,
                              void* d_out, int out_size) {
    const float* o8     = (const float*)d_in[0];
    const float* o16    = (const float*)d_in[1];
    const float* o32    = (const float*)d_in[2];
    const float* labels = (const float*)d_in[3];
    float* out = (float*)d_out;

    k_gt<<<1, 512>>>(labels);
    k_decode<<<BA / 128, 128>>>(o8, o16, o32);
    k_cost<<<NB * 84, 128>>>();
    k_sel1<<<NBG * 4, 128>>>();
    k_sel2<<<NBG, 32>>>();
    k_fgloss<<<(MAXFG + 127) / 128, 128>>>(o8, o16, o32, out, out_size);
}

// round 16
// speedup vs baseline: 1.0322x; 1.0322x over previous
#include <cuda_runtime.h>
#include <math.h>

#define NB 8
#define NA 21504
#define NG 60
#define NC 15
#define BA (NB*NA)
#define NBG (NB*NG)
#define L0N 16384
#define L1N 20480
#define LOG4F 1.3862943611198906f
#define FULLM 0xffffffffu
#define NSEG 16
#define MAXFG 4800
#define CINIT 990000.0f

// ---------------- static device scratch ----------------
__device__ float g_bx[BA], g_by[BA];
__device__ float g_a2[BA], g_b2[BA], g_c2[BA], g_d2s[BA], g_ld2[BA];
__device__ float g_obj[BA], g_S[BA];
__device__ float g_lc[NC*BA];                    // [c][b*A+a] (cand anchors only)
__device__ float2 g_ic[(size_t)NBG*NA];          // compacted {iou, cost}: [b][g][slot]
__device__ int   g_ci[BA];                       // compacted cand anchor idx: [b][slot]
__device__ unsigned long long g_bothA[BA];       // compacted both-bits: [b][slot]
__device__ int   g_ccnt[NB];
__device__ float g_gcx[NBG], g_gcy[NBG], g_ghw[NBG], g_ghh[NBG];
__device__ float g_ga1[NBG], g_gb1[NBG], g_gc1[NBG], g_gd1s[NBG], g_gld1[NBG];
__device__ int   g_gcls[NBG], g_gvalid[NBG];
__device__ float g_pt[NBG*NSEG*10];
__device__ float g_pc[NBG*NSEG*10];
__device__ int   g_pi[NBG*NSEG*10];
__device__ float g_pv[NBG*NSEG*10];
__device__ int   g_segdone[NBG];
__device__ int   g_cnt[BA];
__device__ int   g_mg[BA];
__device__ float g_miou[BA];
__device__ int   g_nfg;
__device__ int   g_done;
__device__ int   g_fgl[MAXFG];
__device__ float g_acc[5];

// ---------------- deterministic pair cost ----------------
__device__ __forceinline__ void pair_cost(
    float ga, float gb, float gc, float gcx, float gcy, float gld1,
    float a2, float b2, float c2, float bx, float by, float lbase,
    float S, float lc, float pb,
    float& iou, float& cost)
{
    float Af = __fadd_rn(ga, a2);
    float Bf = __fadd_rn(gb, b2);
    float Cf = __fadd_rn(gc, c2);
    float dx = __fsub_rn(gcx, bx);
    float dy = __fsub_rn(gcy, by);
    float cc = __fmul_rn(Cf, Cf);
    float den = __fadd_rn(__fmaf_rn(Af, Bf, -cc), 1e-8f);
    float rden = __fdividef(1.f, den);
    float dx2 = __fmul_rn(dx, dx);
    float dy2 = __fmul_rn(dy, dy);
    float t1 = __fmul_rn(__fmul_rn(0.25f, __fmaf_rn(Af, dy2, __fmul_rn(Bf, dx2))), rden);
    float t2 = __fmul_rn(__fmul_rn(-0.5f, __fmul_rn(Cf, __fmul_rn(dx, dy))), rden);
    float t3 = __fmul_rn(0.5f, __fsub_rn(__logf(den), __fadd_rn(gld1, lbase)));
    float bd = fminf(fmaxf(__fadd_rn(__fadd_rn(t1, t2), t3), 1e-8f), 100.f);
    float q = fminf(fmaxf(__fsub_rn(1.f, __expf(-bd)), 1e-20f), 1.f);
    iou = __fsub_rn(1.f, __fmul_rn(q, __frsqrt_rn(q)));
    float base = __fadd_rn(__fadd_rn(S, lc), pb);
    cost = __fmaf_rn(-3.f, __logf(__fadd_rn(iou, 1e-8f)), base);
}

// ---------------- K1b: GT prep + zero accumulators (1 block) ----------------
__global__ void k_gt(const float* __restrict__ labels) {
    int t = threadIdx.x;
    if (t < 5) g_acc[t] = 0.f;
    if (t == 5) g_nfg = 0;
    if (t == 6) g_done = 0;
    if (t >= 8 && t < 8 + NB) g_ccnt[t - 8] = 0;
    if (t < NBG) g_segdone[t] = 0;
    __syncthreads();
    if (t >= NBG) return;
    const float* L = labels + (size_t)t * 6;
    float l0 = L[0], l1 = L[1], l2 = L[2], l3 = L[3], l4 = L[4], l5 = L[5];
    float sum = l0 + l1 + l2 + l3 + l4 + l5;
    int valid = (sum > 0.f) ? 1 : 0;
    float sn, cs; __sincosf(l5, &sn, &cs);
    float w2 = l3*l3/12.0f, h2 = l4*l4/12.0f;
    float a1 = w2*cs*cs + h2*sn*sn;
    float b1 = w2*sn*sn + h2*cs*cs;
    float c1 = (w2 - h2) * cs * sn;
    float d1 = fmaxf(a1*b1 - c1*c1, 0.f);
    float d1s = d1 * __frsqrt_rn(fmaxf(d1, 1e-30f));
    g_gcx[t] = l1; g_gcy[t] = l2;
    g_ghw[t] = 0.5f * l3; g_ghh[t] = 0.5f * l4;
    g_ga1[t] = a1; g_gb1[t] = b1; g_gc1[t] = c1;
    g_gd1s[t] = d1s;
    g_gld1[t] = __logf(fmaxf(d1s, 1e-35f));
    g_gcls[t] = (int)l0;
    g_gvalid[t] = valid;
    if (valid) atomicAdd(&g_acc[4], 1.f);
}

// ---------------- K1: decode + cand/both + compaction + obj-BCE fold ----------------
__global__ void k_decode(const float* __restrict__ o8,
                         const float* __restrict__ o16,
                         const float* __restrict__ o32) {
    int t = blockIdx.x * blockDim.x + threadIdx.x;
    int b = t / NA;
    int a = t - b * NA;
    int tid = threadIdx.x;
    int lane = tid & 31;
    g_cnt[t] = 0;
    __shared__ float s_cx[NG], s_cy[NG], s_hw[NG], s_hh[NG];
    if (tid < NG) {
        int gi = b * NG + tid;
        int v = g_gvalid[gi];
        s_cx[tid] = v ? g_gcx[gi] : 3.0e9f;
        s_cy[tid] = v ? g_gcy[gi] : 3.0e9f;
        s_hw[tid] = g_ghw[gi]; s_hh[tid] = g_ghh[gi];
    }
    __syncthreads();
    const float* src; int hw, i; float st; int gx, gy;
    if (a < L0N)       { src = o8;  hw = 16384; i = a;        st = 8.f;  gx = i & 127; gy = i >> 7; }
    else if (a < L1N)  { src = o16; hw = 4096;  i = a - L0N;  st = 16.f; gx = i & 63;  gy = i >> 6; }
    else               { src = o32; hw = 1024;  i = a - L1N;  st = 32.f; gx = i & 31;  gy = i >> 5; }
    const float* p0 = src + (size_t)b * 21 * hw + i;
    float r0 = p0[0], r1 = p0[hw], r2 = p0[2*hw], r3 = p0[3*hw], r4 = p0[4*hw], r5 = p0[5*hw];
    float bx = (r0 + (float)gx) * st;
    float by = (r1 + (float)gy) * st;
    float bw = __expf(r2) * st;
    float bh = __expf(r3) * st;
    float sn, cs; __sincosf(r4, &sn, &cs);
    float w2 = bw * bw / 12.0f, h2 = bh * bh / 12.0f;
    float a2 = w2*cs*cs + h2*sn*sn;
    float b2 = w2*sn*sn + h2*cs*cs;
    float c2 = (w2 - h2) * cs * sn;
    float d2 = fmaxf(a2*b2 - c2*c2, 0.f);
    float d2s = d2 * __frsqrt_rn(fmaxf(d2, 1e-30f));
    g_bx[t] = bx; g_by[t] = by;
    g_a2[t] = a2; g_b2[t] = b2; g_c2[t] = c2;
    g_d2s[t] = d2s;
    g_ld2[t] = __logf(fmaxf(d2s, 1e-35f));
    g_obj[t] = r5;

    float xc = ((float)gx + 0.5f) * st;
    float yc = ((float)gy + 0.5f) * st;
    float rad = 2.5f * st;
    unsigned long long both = 0ULL;
    bool cand = false;
    #pragma unroll 4
    for (int g = 0; g < NG; g++) {
        float dx = fabsf(xc - s_cx[g]);
        float dy = fabsf(yc - s_cy[g]);
        bool ib = (dx < s_hw[g]) & (dy < s_hh[g]);
        bool ic = (dx < rad) & (dy < rad);
        cand |= ib | ic;
        if (ib & ic) both |= (1ULL << g);
    }
    unsigned mask = __ballot_sync(FULLM, cand);
    if (mask) {
        int base;
        if (lane == 0) base = atomicAdd(&g_ccnt[b], __popc(mask));
        base = __shfl_sync(FULLM, base, 0);
        if (cand) {
            int slot = base + __popc(mask & ((1u << lane) - 1u));
            g_ci[b * NA + slot] = a;
            g_bothA[b * NA + slot] = both;
        }
    }
    if (cand) {
        float so = __fdividef(1.f, 1.f + __expf(-r5));
        float S = 0.f;
        #pragma unroll
        for (int c = 0; c < NC; c++) {
            float x = p0[(6 + c) * hw];
            float sc = __fdividef(1.f, 1.f + __expf(-x));
            float q = sc * so;
            float p = q * __frsqrt_rn(fmaxf(q, 1e-30f));
            p = fminf(fmaxf(p, 1e-7f), 1.f - 1e-7f);
            float lg = __logf(1.f - p);
            float lp = __logf(p);
            S -= lg;
            g_lc[c * BA + t] = lg - lp;
        }
        g_S[t] = S;
    }
    float lo = fmaxf(r5, 0.f) + __logf(1.f + __expf(-fabsf(r5)));
    #pragma unroll
    for (int o = 16; o > 0; o >>= 1) lo += __shfl_down_sync(FULLM, lo, o);
    __shared__ float sred[4];
    int w = tid >> 5;
    if (lane == 0) sred[w] = lo;
    __syncthreads();
    if (tid == 0)
        atomicAdd(&g_acc[1], sred[0] + sred[1] + sred[2] + sred[3]);
}

// ---------------- K2: cost over compacted slots (grid-stride) ----------------
__global__ void k_cost() {
    int b = blockIdx.x / 84;
    int blk = blockIdx.x - b * 84;
    int tid = threadIdx.x;
    __shared__ float s_cx[NG], s_cy[NG];
    __shared__ float s_a1[NG], s_b1[NG], s_c1[NG], s_ld1[NG];
    __shared__ int   s_cls[NG], s_val[NG];
    if (tid < NG) {
        int gi = b * NG + tid;
        s_val[tid] = g_gvalid[gi];
        s_cx[tid] = g_gcx[gi]; s_cy[tid] = g_gcy[gi];
        s_a1[tid] = g_ga1[gi]; s_b1[tid] = g_gb1[gi];
        s_c1[tid] = g_gc1[gi]; s_ld1[tid] = g_gld1[gi];
        s_cls[tid] = g_gcls[gi];
    }
    __syncthreads();
    int cnt = g_ccnt[b];
    for (int slot = blk * 128 + tid; slot < cnt; slot += 84 * 128) {
        int a = g_ci[b * NA + slot];
        int t = b * NA + a;
        unsigned long long both = g_bothA[b * NA + slot];
        float bx = g_bx[t], by = g_by[t];
        float a2 = g_a2[t], b2 = g_b2[t], c2 = g_c2[t];
        float S = g_S[t];
        float lbase = g_ld2[t] + LOG4F;
        size_t rowbase = (size_t)b * NG * NA + slot;
        for (int g = 0; g < NG; g++) {
            if (!s_val[g]) continue;
            float lc = g_lc[s_cls[g] * BA + t];
            float pb = ((both >> g) & 1ULL) ? 0.f : 1e5f;
            float iou, cost;
            pair_cost(s_a1[g], s_b1[g], s_c1[g], s_cx[g], s_cy[g], s_ld1[g],
                      a2, b2, c2, bx, by, lbase, S, lc, pb, iou, cost);
            g_ic[rowbase + (size_t)g * NA] = make_float2(iou, cost);
        }
    }
}

// ---------------- selection helpers ----------------
__device__ __forceinline__ bool pless(float c1, int i1, float c2, int i2) {
    return (c1 < c2) || (c1 == c2 && i1 < i2);
}
__device__ __forceinline__ void wins_top(float& tv, int lane, float c) {
    unsigned bm = __ballot_sync(FULLM, (lane < 10) && (c > tv)) & 0x3FFu;
    if (bm) {
        int p = __ffs(bm) - 1;
        float up = __shfl_up_sync(FULLM, tv, 1);
        if (lane < 10 && lane >= p) tv = (lane == p) ? c : up;
    }
}
__device__ __forceinline__ void wins_bot3(float& bcv, int& biv, float& bov,
                                          int lane, float c, int i, float io) {
    unsigned bm = __ballot_sync(FULLM, (lane < 10) && pless(c, i, bcv, biv)) & 0x3FFu;
    if (bm) {
        int p = __ffs(bm) - 1;
        float uc = __shfl_up_sync(FULLM, bcv, 1);
        int   ui = __shfl_up_sync(FULLM, biv, 1);
        float uo = __shfl_up_sync(FULLM, bov, 1);
        if (lane < 10 && lane >= p) {
            bcv = (lane == p) ? c : uc;
            biv = (lane == p) ? i : ui;
            bov = (lane == p) ? io : uo;
        }
    }
}

// ---------------- K3: partials over compacted list + fused last-block merge ----------------
__global__ void k_sel1() {
    int bg = blockIdx.x >> 2;
    int part = blockIdx.x & 3;
    if (!g_gvalid[bg]) return;
    int w = threadIdx.x >> 5, lane = threadIdx.x & 31;
    int seg = part * 4 + w;
    int b = bg / NG;
    int cnt = g_ccnt[b];
    const float2* __restrict__ row = g_ic + (size_t)bg * NA;
    const int* __restrict__ ci = g_ci + b * NA;

    float tv = 0.f; float bcv = CINIT; int biv = 0x7fffffff; float bov = 0.f;
    float thr_t = 0.f; float thr_c = CINIT; int thr_i = 0x7fffffff;

    for (int it = 0; it * (NSEG * 32) + seg * 32 < cnt; it++) {
        int slot = it * (NSEG * 32) + seg * 32 + lane;
        bool ok = slot < cnt;
        float2 f = make_float2(0.f, 3.0e38f);
        int idx = 0x7fffffff;
        if (ok) { f = row[slot]; idx = ci[slot]; }
        float e = ok ? f.x : 0.f;
        float c = ok ? f.y : 3.0e38f;
        unsigned mt = __ballot_sync(FULLM, e > thr_t);
        unsigned mc = __ballot_sync(FULLM, (c < thr_c) || (c == thr_c && idx <= thr_i));
        if (mt) {
            do {
                int sidx = __ffs(mt) - 1; mt &= mt - 1;
                wins_top(tv, lane, __shfl_sync(FULLM, e, sidx));
            } while (mt);
            thr_t = __shfl_sync(FULLM, tv, 9);
        }
        if (mc) {
            do {
                int sidx = __ffs(mc) - 1; mc &= mc - 1;
                wins_bot3(bcv, biv, bov, lane,
                          __shfl_sync(FULLM, c, sidx), __shfl_sync(FULLM, idx, sidx),
                          __shfl_sync(FULLM, e, sidx));
            } while (mc);
            thr_c = __shfl_sync(FULLM, bcv, 9);
            thr_i = __shfl_sync(FULLM, biv, 9);
        }
    }
    if (lane < 10) {
        int o = (bg * NSEG + seg) * 10 + lane;
        g_pt[o] = tv; g_pc[o] = bcv; g_pi[o] = biv; g_pv[o] = bov;
    }
    // ---- last-arriving block merges all 16 segment partials (former k_sel2) ----
    __threadfence();
    __syncthreads();
    __shared__ int s_last;
    if (threadIdx.x == 0) s_last = (atomicAdd(&g_segdone[bg], 1) == 3) ? 1 : 0;
    __syncthreads();
    if (!s_last || w != 0) return;

    int g = bg - b * NG;
    const float* __restrict__ pt  = g_pt + (size_t)bg * NSEG * 10;
    const float* __restrict__ pcr = g_pc + (size_t)bg * NSEG * 10;
    const int*   __restrict__ pir = g_pi + (size_t)bg * NSEG * 10;
    const float* __restrict__ pvr = g_pv + (size_t)bg * NSEG * 10;

    tv = 0.f; bcv = CINIT; bov = 0.f; biv = 0x7fffffff;
    thr_t = 0.f; thr_c = CINIT; thr_i = 0x7fffffff;
    #pragma unroll
    for (int i = 0; i < 5; i++) {
        int e = i * 32 + lane;
        bool ok = e < NSEG * 10;
        float a = ok ? pt[e]  : 0.f;
        float c = ok ? pcr[e] : 3.0e38f;
        int  ix = ok ? pir[e] : 0x7fffffff;
        float io = ok ? pvr[e] : 0.f;
        unsigned mt = __ballot_sync(FULLM, a > thr_t);
        unsigned mc = __ballot_sync(FULLM, (c < thr_c) || (c == thr_c && ix < thr_i));
        while (mt) {
            int sidx = __ffs(mt) - 1; mt &= mt - 1;
            wins_top(tv, lane, __shfl_sync(FULLM, a, sidx));
        }
        thr_t = __shfl_sync(FULLM, tv, 9);
        while (mc) {
            int sidx = __ffs(mc) - 1; mc &= mc - 1;
            wins_bot3(bcv, biv, bov, lane,
                      __shfl_sync(FULLM, c, sidx), __shfl_sync(FULLM, ix, sidx),
                      __shfl_sync(FULLM, io, sidx));
        }
        thr_c = __shfl_sync(FULLM, bcv, 9);
        thr_i = __shfl_sync(FULLM, biv, 9);
    }
    float x = (lane < 10) ? tv : 0.f;
    #pragma unroll
    for (int o = 16; o > 0; o >>= 1) x += __shfl_xor_sync(FULLM, x, o);
    int k = (int)x;
    if (k < 1) k = 1;
    if (k > 10) k = 10;
    if (lane < k) {
        int t = b * NA + biv;
        int old = atomicAdd(&g_cnt[t], 1);
        if (old == 0) {
            g_mg[t] = g;
            g_miou[t] = bov;
            int pos = atomicAdd(&g_nfg, 1);
            g_fgl[pos] = t;
        }
    }
}

// ---------------- K5: losses over fg anchors + fused finalize ----------------
__global__ void k_fgloss(const float* __restrict__ o8,
                         const float* __restrict__ o16,
                         const float* __restrict__ o32,
                         float* __restrict__ out, int n) {
    int i = blockIdx.x * blockDim.x + threadIdx.x;
    int nfg = g_nfg;
    float liou = 0.f, lcls = 0.f, lobjc = 0.f, fo = 0.f;
    if (i < nfg) {
        int t = g_fgl[i];
        int b = t / NA;
        int a = t - b * NA;
        int cnt = g_cnt[t];
        int mg; float pi;
        if (cnt == 1) { mg = g_mg[t]; pi = g_miou[t]; }
        else {
            float st; int lvlbase, shx, mskx;
            if (a < L0N)      { st = 8.f;  lvlbase = 0;    shx = 7; mskx = 127; }
            else if (a < L1N) { st = 16.f; lvlbase = L0N;  shx = 6; mskx = 63; }
            else              { st = 32.f; lvlbase = L1N;  shx = 5; mskx = 31; }
            int ii = a - lvlbase;
            float xc = ((float)(ii & mskx) + 0.5f) * st;
            float yc = ((float)(ii >> shx) + 0.5f) * st;
            float rad = 2.5f * st;
            float bx = g_bx[t], by = g_by[t];
            float a2 = g_a2[t], b2 = g_b2[t], c2 = g_c2[t];
            float S = g_S[t];
            float lbase = g_ld2[t] + LOG4F;
            float minc = 3.4e38f; mg = 0; pi = 0.f;
            for (int g = 0; g < NG; g++) {
                int gi = b * NG + g;
                if (!g_gvalid[gi]) continue;
                float gcx = g_gcx[gi], gcy = g_gcy[gi];
                float dxa = fabsf(xc - gcx), dya = fabsf(yc - gcy);
                bool ib = (dxa < g_ghw[gi]) & (dya < g_ghh[gi]);
                bool ic = (dxa < rad) & (dya < rad);
                float pb = (ib & ic) ? 0.f : 1e5f;
                float lc = g_lc[g_gcls[gi] * BA + t];
                float iou, cost;
                pair_cost(g_ga1[gi], g_gb1[gi], g_gc1[gi], gcx, gcy, g_gld1[gi],
                          a2, b2, c2, bx, by, lbase, S, lc, pb, iou, cost);
                if (cost < minc) { minc = cost; mg = g; pi = iou; }
            }
        }
        int gi = b * NG + mg;
        {
            float bx = g_bx[t], by = g_by[t];
            float a2 = g_a2[t], b2 = g_b2[t], c2 = g_c2[t], d2s = g_d2s[t];
            float Af = a2 + g_ga1[gi], Bf = b2 + g_gb1[gi], Cf = c2 + g_gc1[gi];
            float dx = bx - g_gcx[gi], dy = by - g_gcy[gi];
            float den = Af * Bf - Cf * Cf + 1e-8f;
            float rden = __fdividef(1.f, den);
            float t1 = 0.25f * (Af*dy*dy + Bf*dx*dx) * rden;
            float t2 = -0.5f * Cf * dx * dy * rden;
            float t3 = 0.5f * __logf(__fdividef(den, 4.f * g_gd1s[gi] * d2s + 1e-8f));
            float bd = fminf(fmaxf(t1 + t2 + t3, 1e-8f), 100.f);
            float q = fminf(fmaxf(1.f - __expf(-bd), 1e-20f), 1.f);
            float ioum = 1.f - q * __frsqrt_rn(q);
            liou = 1.f - ioum;
        }
        {
            const float* src; int hw, idx;
            if (a < L0N)      { src = o8;  hw = 16384; idx = a; }
            else if (a < L1N) { src = o16; hw = 4096;  idx = a - L0N; }
            else              { src = o32; hw = 1024;  idx = a - L1N; }
            const float* pc = src + ((size_t)b * 21 + 6) * hw + idx;
            int mcls = g_gcls[gi];
            #pragma unroll
            for (int c = 0; c < NC; c++) {
                float x = pc[(size_t)c * hw];
                float tg = (c == mcls) ? pi : 0.f;
                lcls += fmaxf(x, 0.f) - x * tg + __logf(1.f + __expf(-fabsf(x)));
            }
        }
        lobjc = -g_obj[t];
        fo = 1.f;
    }
    #pragma unroll
    for (int o = 16; o > 0; o >>= 1) {
        liou  += __shfl_down_sync(FULLM, liou, o);
        lcls  += __shfl_down_sync(FULLM, lcls, o);
        lobjc += __shfl_down_sync(FULLM, lobjc, o);
        fo    += __shfl_down_sync(FULLM, fo, o);
    }
    if ((threadIdx.x & 31) == 0) {
        atomicAdd(&g_acc[0], liou);
        atomicAdd(&g_acc[1], lobjc);
        atomicAdd(&g_acc[2], lcls);
        atomicAdd(&g_acc[3], fo);
    }
    __syncthreads();
    if (threadIdx.x == 0) {
        __threadfence();
        int prev = atomicAdd(&g_done, 1);
        if (prev == gridDim.x - 1) {
            float nf2 = g_acc[3];
            float nf = fmaxf(nf2, 1.f);
            float li = g_acc[0] / nf;
            float lo = g_acc[1] / nf;
            float lc2 = g_acc[2] / nf;
            float li5 = 5.f * li;
            if (n > 0) out[0] = li5 + lo + lc2;
            if (n > 1) out[1] = li5;
            if (n > 2) out[2] = lo;
            if (n > 3) out[3] = lc2;
            if (n > 4) out[4] = 0.f;
            if (n > 5) out[5] = nf2 / fmaxf(g_acc[4], 1.f);
            for (int j = 6; j < n; j++) out[j] = 0.f;
        }
    }
}

// ---------------- launch ----------------
extern "C" void kernel_launch(void* const* d_in, const int* in_sizes, int n_in,
                              void* d_out, int out_size) {
    const float* o8     = (const float*)d_in[0];
    const float* o16    = (const float*)d_in[1];
    const float* o32    = (const float*)d_in[2];
    const float* labels = (const float*)d_in[3];
    float* out = (float*)d_out;

    k_gt<<<1, 512>>>(labels);
    k_decode<<<BA / 128, 128>>>(o8, o16, o32);
    k_cost<<<NB * 84, 128>>>();
    k_sel1<<<NBG * 4, 128>>>();
    k_fgloss<<<(MAXFG + 127) / 128, 128>>>(o8, o16, o32, out, out_size);
}